// round 2
// baseline (speedup 1.0000x reference)
#include <cuda_runtime.h>
#include <cuda_bf16.h>
#include <cstdint>

#define HDIM 128

// ---------------- static scratch (no allocations allowed) ----------------
#define NA_MAX 50000
#define NB_MAX 30000
#define EA_MAX 600000
#define EB_MAX 300000

__device__ float g_bufA0[NA_MAX * HDIM];
__device__ float g_bufA1[NA_MAX * HDIM];
__device__ float g_bufB0[NB_MAX * HDIM];
__device__ float g_bufB1[NB_MAX * HDIM];

__device__ int g_cntOutA[NA_MAX];
__device__ int g_cntInA[NA_MAX];
__device__ int g_fillA[NA_MAX];
__device__ int g_rowpA[NA_MAX + 1];
__device__ int g_colA[EA_MAX];
__device__ float g_nsA[NA_MAX];
__device__ float g_ndA[NA_MAX];

__device__ int g_cntOutB[NB_MAX];
__device__ int g_cntInB[NB_MAX];
__device__ int g_fillB[NB_MAX];
__device__ int g_rowpB[NB_MAX + 1];
__device__ int g_colB[EB_MAX];
__device__ float g_nsB[NB_MAX];
__device__ float g_ndB[NB_MAX];

// ---------------- small graph-prep kernels ----------------
__global__ void zero_int_kernel(int* p, int n) {
    int i = blockIdx.x * blockDim.x + threadIdx.x;
    if (i < n) p[i] = 0;
}

__global__ void count_deg_kernel(const int* __restrict__ src, const int* __restrict__ dst,
                                 int E, int* cntOut, int* cntIn) {
    int i = blockIdx.x * blockDim.x + threadIdx.x;
    if (i < E) {
        atomicAdd(&cntOut[src[i]], 1);
        atomicAdd(&cntIn[dst[i]], 1);
    }
}

__global__ void norms_kernel(const int* __restrict__ cntOut, const int* __restrict__ cntIn,
                             float* ns, float* nd, int n) {
    int i = blockIdx.x * blockDim.x + threadIdx.x;
    if (i < n) {
        ns[i] = rsqrtf((float)(cntOut[i] + 1));  // +1 self loop
        nd[i] = rsqrtf((float)(cntIn[i] + 1));
    }
}

// Single-block exclusive scan of cnt[0..n) -> rowp[0..n], rowp[0]=0.
__global__ void scan_kernel(const int* __restrict__ cnt, int* rowp, int n) {
    __shared__ int sh[1024];
    __shared__ int carry;
    if (threadIdx.x == 0) { carry = 0; rowp[0] = 0; }
    __syncthreads();
    for (int base = 0; base < n; base += 1024) {
        int i = base + threadIdx.x;
        int v = (i < n) ? cnt[i] : 0;
        sh[threadIdx.x] = v;
        __syncthreads();
        for (int off = 1; off < 1024; off <<= 1) {
            int t = (threadIdx.x >= off) ? sh[threadIdx.x - off] : 0;
            __syncthreads();
            sh[threadIdx.x] += t;
            __syncthreads();
        }
        if (i < n) rowp[i + 1] = carry + sh[threadIdx.x];
        __syncthreads();
        if (threadIdx.x == 0) carry += sh[1023];
        __syncthreads();
    }
}

__global__ void csr_fill_kernel(const int* __restrict__ src, const int* __restrict__ dst,
                                int E, const int* __restrict__ rowp, int* fill, int* col) {
    int i = blockIdx.x * blockDim.x + threadIdx.x;
    if (i < E) {
        int d = dst[i];
        int pos = atomicAdd(&fill[d], 1);
        col[rowp[d] + pos] = src[i];
    }
}

// ---------------- SGEMM: Y[M,128] = (X[M,K] * ns[row]) @ W[K,128] ----------------
// BM=128, BN=128 (full width), BK=8, 256 threads, 8x8 microtile.
__global__ __launch_bounds__(256) void sgemm_scaled_kernel(
    const float* __restrict__ X, const float* __restrict__ ns,
    const float* __restrict__ W, float* __restrict__ Y,
    int M, int K) {
    __shared__ float As[8][128];
    __shared__ float Bs[8][128];

    const int tid = threadIdx.x;
    const int block_row = blockIdx.x * 128;
    const int ty = tid >> 4;   // 0..15
    const int tx = tid & 15;   // 0..15

    // A load: each thread -> 4 floats: row = tid/2 (0..127), colgroup = (tid&1)*4
    const int arow = tid >> 1;
    const int acol = (tid & 1) * 4;
    // B load: row k = tid/32 (0..7), col = (tid%32)*4
    const int brow = tid >> 5;
    const int bcol = (tid & 31) * 4;

    const int grow = block_row + arow;
    const float ascale = (grow < M) ? ns[grow] : 0.0f;

    float acc[8][8];
    #pragma unroll
    for (int i = 0; i < 8; i++)
        #pragma unroll
        for (int j = 0; j < 8; j++) acc[i][j] = 0.0f;

    for (int k0 = 0; k0 < K; k0 += 8) {
        float4 a = make_float4(0.f, 0.f, 0.f, 0.f);
        if (grow < M) a = *(const float4*)&X[(size_t)grow * K + k0 + acol];
        As[acol + 0][arow] = a.x * ascale;
        As[acol + 1][arow] = a.y * ascale;
        As[acol + 2][arow] = a.z * ascale;
        As[acol + 3][arow] = a.w * ascale;

        float4 b = *(const float4*)&W[(size_t)(k0 + brow) * HDIM + bcol];
        *(float4*)&Bs[brow][bcol] = b;
        __syncthreads();

        #pragma unroll
        for (int k = 0; k < 8; k++) {
            float4 ra0 = *(const float4*)&As[k][ty * 8];
            float4 ra1 = *(const float4*)&As[k][ty * 8 + 4];
            float4 rb0 = *(const float4*)&Bs[k][tx * 8];
            float4 rb1 = *(const float4*)&Bs[k][tx * 8 + 4];
            float ra[8] = {ra0.x, ra0.y, ra0.z, ra0.w, ra1.x, ra1.y, ra1.z, ra1.w};
            float rb[8] = {rb0.x, rb0.y, rb0.z, rb0.w, rb1.x, rb1.y, rb1.z, rb1.w};
            #pragma unroll
            for (int i = 0; i < 8; i++)
                #pragma unroll
                for (int j = 0; j < 8; j++)
                    acc[i][j] = fmaf(ra[i], rb[j], acc[i][j]);
        }
        __syncthreads();
    }

    #pragma unroll
    for (int i = 0; i < 8; i++) {
        int gr = block_row + ty * 8 + i;
        if (gr < M) {
            float4 o0 = make_float4(acc[i][0], acc[i][1], acc[i][2], acc[i][3]);
            float4 o1 = make_float4(acc[i][4], acc[i][5], acc[i][6], acc[i][7]);
            *(float4*)&Y[(size_t)gr * HDIM + tx * 8]     = o0;
            *(float4*)&Y[(size_t)gr * HDIM + tx * 8 + 4] = o1;
        }
    }
}

// ---------------- aggregation: out[i] = relu?((y[i] + sum_nbr y[nbr]) * nd[i] + b) ----------------
__global__ __launch_bounds__(256) void aggregate_kernel(
    const float* __restrict__ y,
    const int* __restrict__ rowp, const int* __restrict__ col,
    const float* __restrict__ nd, const float* __restrict__ bias,
    float* __restrict__ out, int n, int do_relu) {
    int warp = (blockIdx.x * blockDim.x + threadIdx.x) >> 5;
    int lane = threadIdx.x & 31;
    if (warp >= n) return;

    const float4* yrow = (const float4*)(y + (size_t)warp * HDIM);
    float4 acc = yrow[lane];  // self loop

    int s = __ldg(&rowp[warp]);
    int e = __ldg(&rowp[warp + 1]);
    for (int i = s; i < e; i++) {
        int nb = __ldg(&col[i]);
        float4 v = *((const float4*)(y + (size_t)nb * HDIM) + lane);
        acc.x += v.x; acc.y += v.y; acc.z += v.z; acc.w += v.w;
    }
    float sc = nd[warp];
    float4 b = ((const float4*)bias)[lane];
    float4 r;
    r.x = fmaf(acc.x, sc, b.x);
    r.y = fmaf(acc.y, sc, b.y);
    r.z = fmaf(acc.z, sc, b.z);
    r.w = fmaf(acc.w, sc, b.w);
    if (do_relu) {
        r.x = fmaxf(r.x, 0.f); r.y = fmaxf(r.y, 0.f);
        r.z = fmaxf(r.z, 0.f); r.w = fmaxf(r.w, 0.f);
    }
    ((float4*)(out + (size_t)warp * HDIM))[lane] = r;
}

// ---------------- host orchestration ----------------
static inline int cdiv(int a, int b) { return (a + b - 1) / b; }

extern "C" void kernel_launch(void* const* d_in, const int* in_sizes, int n_in,
                              void* d_out, int out_size) {
    const float* feat_a = (const float*)d_in[0];
    const float* feat_b = (const float*)d_in[1];
    const int* src_a = (const int*)d_in[2];
    const int* dst_a = (const int*)d_in[3];
    const int* src_b = (const int*)d_in[4];
    const int* dst_b = (const int*)d_in[5];
    const float* Wa0 = (const float*)d_in[6];
    const float* ba0 = (const float*)d_in[7];
    const float* Wa1 = (const float*)d_in[8];
    const float* ba1 = (const float*)d_in[9];
    const float* Wb0 = (const float*)d_in[10];
    const float* bb0 = (const float*)d_in[11];
    const float* Wb1 = (const float*)d_in[12];
    const float* bb1 = (const float*)d_in[13];

    const int H = in_sizes[7];                 // 128
    const int DA = in_sizes[6] / H;            // 256
    const int NA = in_sizes[0] / DA;           // 50000
    const int EA = in_sizes[2];                // 600000
    const int DB = in_sizes[10] / H;           // 128
    const int NB = in_sizes[1] / DB;           // 30000
    const int EB = in_sizes[4];                // 300000

    float* out = (float*)d_out;
    float* out_a = out;
    float* out_b = out + (size_t)NA * HDIM;

    // resolve device-global scratch (non-stream API; capture-safe)
    float *bufA0, *bufA1, *bufB0, *bufB1, *nsA, *ndA, *nsB, *ndB;
    int *cntOutA, *cntInA, *fillA, *rowpA, *colA;
    int *cntOutB, *cntInB, *fillB, *rowpB, *colB;
    cudaGetSymbolAddress((void**)&bufA0, g_bufA0);
    cudaGetSymbolAddress((void**)&bufA1, g_bufA1);
    cudaGetSymbolAddress((void**)&bufB0, g_bufB0);
    cudaGetSymbolAddress((void**)&bufB1, g_bufB1);
    cudaGetSymbolAddress((void**)&nsA, g_nsA);
    cudaGetSymbolAddress((void**)&ndA, g_ndA);
    cudaGetSymbolAddress((void**)&nsB, g_nsB);
    cudaGetSymbolAddress((void**)&ndB, g_ndB);
    cudaGetSymbolAddress((void**)&cntOutA, g_cntOutA);
    cudaGetSymbolAddress((void**)&cntInA, g_cntInA);
    cudaGetSymbolAddress((void**)&fillA, g_fillA);
    cudaGetSymbolAddress((void**)&rowpA, g_rowpA);
    cudaGetSymbolAddress((void**)&colA, g_colA);
    cudaGetSymbolAddress((void**)&cntOutB, g_cntOutB);
    cudaGetSymbolAddress((void**)&cntInB, g_cntInB);
    cudaGetSymbolAddress((void**)&fillB, g_fillB);
    cudaGetSymbolAddress((void**)&rowpB, g_rowpB);
    cudaGetSymbolAddress((void**)&colB, g_colB);

    const int T = 256;

    // ---- graph prep A ----
    zero_int_kernel<<<cdiv(NA, T), T>>>(cntOutA, NA);
    zero_int_kernel<<<cdiv(NA, T), T>>>(cntInA, NA);
    zero_int_kernel<<<cdiv(NA, T), T>>>(fillA, NA);
    count_deg_kernel<<<cdiv(EA, T), T>>>(src_a, dst_a, EA, cntOutA, cntInA);
    norms_kernel<<<cdiv(NA, T), T>>>(cntOutA, cntInA, nsA, ndA, NA);
    scan_kernel<<<1, 1024>>>(cntInA, rowpA, NA);
    csr_fill_kernel<<<cdiv(EA, T), T>>>(src_a, dst_a, EA, rowpA, fillA, colA);

    // ---- graph prep B ----
    zero_int_kernel<<<cdiv(NB, T), T>>>(cntOutB, NB);
    zero_int_kernel<<<cdiv(NB, T), T>>>(cntInB, NB);
    zero_int_kernel<<<cdiv(NB, T), T>>>(fillB, NB);
    count_deg_kernel<<<cdiv(EB, T), T>>>(src_b, dst_b, EB, cntOutB, cntInB);
    norms_kernel<<<cdiv(NB, T), T>>>(cntOutB, cntInB, nsB, ndB, NB);
    scan_kernel<<<1, 1024>>>(cntInB, rowpB, NB);
    csr_fill_kernel<<<cdiv(EB, T), T>>>(src_b, dst_b, EB, rowpB, fillB, colB);

    // ---- ntype A ----
    sgemm_scaled_kernel<<<cdiv(NA, 128), 256>>>(feat_a, nsA, Wa0, bufA0, NA, DA);
    aggregate_kernel<<<cdiv(NA * 32, 256), 256>>>(bufA0, rowpA, colA, ndA, ba0, bufA1, NA, 1);
    sgemm_scaled_kernel<<<cdiv(NA, 128), 256>>>(bufA1, nsA, Wa1, bufA0, NA, H);
    aggregate_kernel<<<cdiv(NA * 32, 256), 256>>>(bufA0, rowpA, colA, ndA, ba1, out_a, NA, 0);

    // ---- ntype B ----
    sgemm_scaled_kernel<<<cdiv(NB, 128), 256>>>(feat_b, nsB, Wb0, bufB0, NB, DB);
    aggregate_kernel<<<cdiv(NB * 32, 256), 256>>>(bufB0, rowpB, colB, ndB, bb0, bufB1, NB, 1);
    sgemm_scaled_kernel<<<cdiv(NB, 128), 256>>>(bufB1, nsB, Wb1, bufB0, NB, H);
    aggregate_kernel<<<cdiv(NB * 32, 256), 256>>>(bufB0, rowpB, colB, ndB, bb1, out_b, NB, 0);

    (void)n_in; (void)out_size;
}